// round 11
// baseline (speedup 1.0000x reference)
#include <cuda_runtime.h>
#include <cuda_bf16.h>
#include <cstdint>

// Problem constants (fixed by the dataset)
#define N_NODES 100000
#define N_EDGES 1600000
#define N_FEAT  128
#define HIDDEN  64
#define N_OUT   10
#define N_GRAPHS 64

#define SCAN_B 1024
#define N_SCAN_BLOCKS ((N_NODES + SCAN_B - 1) / SCAN_B)   // 98

// ---------------- device scratch (static, no allocation) ----------------
__device__ int    g_deg[N_NODES];
__device__ float  g_dis[N_NODES];
__device__ int    g_rowptr[N_NODES + 1];
__device__ int    g_cursor[N_NODES];
__device__ int    g_scan_tmp[N_NODES];
__device__ int    g_bsum[N_SCAN_BLOCKS];
__device__ __align__(16) int2  g_csr_pack[N_EDGES];
__device__ __align__(16) float g_tmpA[(size_t)N_NODES * HIDDEN];
__device__ __align__(16) float g_tmpB[(size_t)N_NODES * HIDDEN];
__device__ float  g_pool_sums[N_GRAPHS * HIDDEN];
__device__ float  g_pool_cnt[N_GRAPHS];

// ---------------- init / CSR build (proven, round 8) --------------------
__global__ void init_kernel() {
    int i = blockIdx.x * blockDim.x + threadIdx.x;
    if (i < N_NODES) g_deg[i] = 1;
    if (i < N_GRAPHS * HIDDEN) g_pool_sums[i] = 0.f;
    if (i < N_GRAPHS) g_pool_cnt[i] = 0.f;
}

__global__ void count_kernel(const int* __restrict__ ei) {
    int e = blockIdx.x * blockDim.x + threadIdx.x;
    if (e < N_EDGES) atomicAdd(&g_deg[ei[e + N_EDGES]], 1);
}

__global__ void scan1_kernel() {
    __shared__ int s[SCAN_B];
    int tid = threadIdx.x;
    int i = blockIdx.x * SCAN_B + tid;
    int deg = (i < N_NODES) ? g_deg[i] : 1;
    if (i < N_NODES) g_dis[i] = rsqrtf((float)deg);
    int v = deg - 1;
    s[tid] = v;
    __syncthreads();
    #pragma unroll
    for (int off = 1; off < SCAN_B; off <<= 1) {
        int t = (tid >= off) ? s[tid - off] : 0;
        __syncthreads();
        s[tid] += t;
        __syncthreads();
    }
    if (i < N_NODES) g_scan_tmp[i] = s[tid] - v;
    if (tid == SCAN_B - 1) g_bsum[blockIdx.x] = s[tid];
}

__global__ void scan3_kernel() {
    __shared__ int base;
    if (threadIdx.x == 0) {
        int run = 0;
        for (int b = 0; b < blockIdx.x; b++) run += g_bsum[b];
        base = run;
        if (blockIdx.x == 0) g_rowptr[N_NODES] = N_EDGES;
    }
    __syncthreads();
    int i = blockIdx.x * SCAN_B + threadIdx.x;
    if (i < N_NODES) {
        int v = g_scan_tmp[i] + base;
        g_rowptr[i] = v;
        g_cursor[i] = v;
    }
}

__global__ void fill_kernel(const int* __restrict__ ei) {
    int e = blockIdx.x * blockDim.x + threadIdx.x;
    if (e < N_EDGES) {
        int r = ei[e];
        int c = ei[e + N_EDGES];
        int pos = atomicAdd(&g_cursor[c], 1);
        float nr = g_dis[r] * g_dis[c];
        g_csr_pack[pos] = make_int2(r, __float_as_int(nr));
    }
}

// ---------------- mma.sync bf16 split-2 GEMM -----------------------------
// C[M,64] = A[M,K] @ W[K,64], fp32 I/O.
// a = ah + al (bf16 hi + bf16 residual); D = Ah*Bh + Ah*Bl + Al*Bh (fp32 acc).
// CTA: 128 rows x 64 cols, 512 threads = 16 warps (8 m-groups x 2 n-groups).
// Warp tile 16x32 = 1 m16 x 4 n8 mma tiles, k-step 16.
// A (hi,lo) and B=W^T (hi,lo) staged once in dynamic smem, stride K+8 bf16.

__device__ __forceinline__ void mma_bf16(float* d, const uint32_t* a,
                                         uint32_t b0, uint32_t b1) {
    asm volatile(
        "mma.sync.aligned.m16n8k16.row.col.f32.bf16.bf16.f32 "
        "{%0,%1,%2,%3}, {%4,%5,%6,%7}, {%8,%9}, {%0,%1,%2,%3};"
        : "+f"(d[0]), "+f"(d[1]), "+f"(d[2]), "+f"(d[3])
        : "r"(a[0]), "r"(a[1]), "r"(a[2]), "r"(a[3]), "r"(b0), "r"(b1));
}

__device__ __forceinline__ uint32_t pack_bf16(__nv_bfloat16 lo, __nv_bfloat16 hi) {
    return ((uint32_t)__bfloat16_as_ushort(hi) << 16) | __bfloat16_as_ushort(lo);
}

template <int K>
__global__ __launch_bounds__(512, 2)
void gemm_mma_kernel(const float* __restrict__ x, const float* __restrict__ W,
                     int sel, int M) {
    constexpr int ST = K + 8;        // bf16 row stride (bank-spread)
    extern __shared__ __nv_bfloat16 smem[];
    __nv_bfloat16* Ah = smem;
    __nv_bfloat16* Al = Ah + 128 * ST;
    __nv_bfloat16* Bh = Al + 128 * ST;
    __nv_bfloat16* Bl = Bh + 64 * ST;

    const float* __restrict__ A = (sel == 0) ? x : (const float*)g_tmpB;
    float* __restrict__ C = g_tmpA;

    const int tid = threadIdx.x;
    const int row0 = blockIdx.x * 128;

    // ---- stage A block: fp32 -> bf16 hi + residual lo ----
    for (int u = tid; u < 128 * (K / 2); u += 512) {
        int row = u / (K / 2);
        int kp  = u - row * (K / 2);
        float2 v = make_float2(0.f, 0.f);
        int grow = row0 + row;
        if (grow < M) v = *(const float2*)(A + (size_t)grow * K + kp * 2);
        __nv_bfloat16 h0 = __float2bfloat16(v.x);
        __nv_bfloat16 h1 = __float2bfloat16(v.y);
        __nv_bfloat16 l0 = __float2bfloat16(v.x - __bfloat162float(h0));
        __nv_bfloat16 l1 = __float2bfloat16(v.y - __bfloat162float(h1));
        *(uint32_t*)(Ah + row * ST + kp * 2) = pack_bf16(h0, h1);
        *(uint32_t*)(Al + row * ST + kp * 2) = pack_bf16(l0, l1);
    }

    // ---- stage B = W^T: Bh/Bl[n][k] ----
    for (int u = tid; u < 64 * (K / 2); u += 512) {
        int n  = u / (K / 2);
        int kp = u - n * (K / 2);
        float w0 = W[(kp * 2) * 64 + n];
        float w1 = W[(kp * 2 + 1) * 64 + n];
        __nv_bfloat16 h0 = __float2bfloat16(w0);
        __nv_bfloat16 h1 = __float2bfloat16(w1);
        __nv_bfloat16 l0 = __float2bfloat16(w0 - __bfloat162float(h0));
        __nv_bfloat16 l1 = __float2bfloat16(w1 - __bfloat162float(h1));
        *(uint32_t*)(Bh + n * ST + kp * 2) = pack_bf16(h0, h1);
        *(uint32_t*)(Bl + n * ST + kp * 2) = pack_bf16(l0, l1);
    }
    __syncthreads();

    // ---- main loop ----
    const int lane = tid & 31;
    const int wid  = tid >> 5;          // 0..15
    const int rbase = (wid >> 1) * 16;  // warp rows: rbase..rbase+15
    const int cbase = (wid & 1) * 32;   // warp cols: cbase..cbase+31
    const int lr = lane >> 2;           // 0..7
    const int lc = (lane & 3) * 2;      // 0,2,4,6

    float acc[4][4];
    #pragma unroll
    for (int tn = 0; tn < 4; tn++)
        #pragma unroll
        for (int j = 0; j < 4; j++) acc[tn][j] = 0.f;

    #pragma unroll
    for (int s = 0; s < K / 16; s++) {
        const int kb = s * 16;
        uint32_t ah[4], al[4];
        {
            const __nv_bfloat16* p = Ah + (rbase + lr) * ST + kb + lc;
            const __nv_bfloat16* q = Al + (rbase + lr) * ST + kb + lc;
            ah[0] = *(const uint32_t*)(p);
            ah[1] = *(const uint32_t*)(p + 8 * ST);
            ah[2] = *(const uint32_t*)(p + 8);
            ah[3] = *(const uint32_t*)(p + 8 * ST + 8);
            al[0] = *(const uint32_t*)(q);
            al[1] = *(const uint32_t*)(q + 8 * ST);
            al[2] = *(const uint32_t*)(q + 8);
            al[3] = *(const uint32_t*)(q + 8 * ST + 8);
        }
        uint32_t bh[4][2], bl[4][2];
        #pragma unroll
        for (int tn = 0; tn < 4; tn++) {
            const __nv_bfloat16* p = Bh + (cbase + tn * 8 + lr) * ST + kb + lc;
            const __nv_bfloat16* q = Bl + (cbase + tn * 8 + lr) * ST + kb + lc;
            bh[tn][0] = *(const uint32_t*)(p);
            bh[tn][1] = *(const uint32_t*)(p + 8);
            bl[tn][0] = *(const uint32_t*)(q);
            bl[tn][1] = *(const uint32_t*)(q + 8);
        }
        #pragma unroll
        for (int tn = 0; tn < 4; tn++) {
            mma_bf16(acc[tn], ah, bh[tn][0], bh[tn][1]);
            mma_bf16(acc[tn], ah, bl[tn][0], bl[tn][1]);
            mma_bf16(acc[tn], al, bh[tn][0], bh[tn][1]);
        }
    }

    // ---- epilogue ----
    #pragma unroll
    for (int tn = 0; tn < 4; tn++) {
        int r = row0 + rbase + lr;
        int c = cbase + tn * 8 + lc;
        if (r < M)
            *(float2*)(C + (size_t)r * 64 + c) =
                make_float2(acc[tn][0], acc[tn][1]);
        if (r + 8 < M)
            *(float2*)(C + (size_t)(r + 8) * 64 + c) =
                make_float2(acc[tn][2], acc[tn][3]);
    }
}

// ---------------- aggregation (proven round-8 form) ----------------------
__global__ void aggregate_kernel(const float* __restrict__ bias, int relu) {
    int warp = (blockIdx.x * blockDim.x + threadIdx.x) >> 5;
    if (warp >= N_NODES) return;
    int lane = threadIdx.x & 31;

    const float* __restrict__ hW = g_tmpA;
    float* __restrict__ out = g_tmpB;

    int start = g_rowptr[warp];
    int end   = g_rowptr[warp + 1];
    float d = g_dis[warp];
    float w = d * d;

    float2 s = *(const float2*)(hW + (size_t)warp * 64 + lane * 2);
    float ax = s.x * w, ay = s.y * w;

    for (int k = start; k < end; k++) {
        int2 p = g_csr_pack[k];
        float nr = __int_as_float(p.y);
        float2 v = *(const float2*)(hW + (size_t)p.x * 64 + lane * 2);
        ax += v.x * nr;
        ay += v.y * nr;
    }

    ax += bias[lane * 2];
    ay += bias[lane * 2 + 1];
    if (relu) { ax = fmaxf(ax, 0.f); ay = fmaxf(ay, 0.f); }
    *(float2*)(out + (size_t)warp * 64 + lane * 2) = make_float2(ax, ay);
}

// ---------------- mean pool over sorted batch ----------------------------
__global__ void pool_kernel(const int* __restrict__ batch) {
    const float* __restrict__ h = g_tmpB;
    int col  = threadIdx.x & 63;
    int slot = threadIdx.x >> 6;
    int n0 = blockIdx.x * 512 + slot * 128;
    if (n0 >= N_NODES) return;
    int n1 = min(n0 + 128, N_NODES);

    float acc = 0.f, cnt = 0.f;
    int cur = batch[n0];
    for (int i = n0; i < n1; i++) {
        int g = batch[i];
        if (g != cur) {
            atomicAdd(&g_pool_sums[cur * 64 + col], acc);
            if (col == 0) atomicAdd(&g_pool_cnt[cur], cnt);
            cur = g; acc = 0.f; cnt = 0.f;
        }
        acc += h[(size_t)i * 64 + col];
        cnt += 1.f;
    }
    atomicAdd(&g_pool_sums[cur * 64 + col], acc);
    if (col == 0) atomicAdd(&g_pool_cnt[cur], cnt);
}

// ---------------- final linear -------------------------------------------
__global__ void final_kernel(const float* __restrict__ Wlin,
                             const float* __restrict__ blin,
                             float* __restrict__ out) {
    int tid = threadIdx.x;
    if (tid >= N_GRAPHS * N_OUT) return;
    int g = tid / N_OUT;
    int o = tid % N_OUT;
    float inv = 1.f / fmaxf(g_pool_cnt[g], 1.f);
    float acc = blin[o];
    #pragma unroll
    for (int c = 0; c < 64; c++)
        acc += g_pool_sums[g * 64 + c] * inv * Wlin[c * N_OUT + o];
    out[g * N_OUT + o] = acc;
}

// ---------------- launch --------------------------------------------------
extern "C" void kernel_launch(void* const* d_in, const int* in_sizes, int n_in,
                              void* d_out, int out_size) {
    const float* x    = (const float*)d_in[0];
    const int*   ei   = (const int*)d_in[1];
    const int*   batch= (const int*)d_in[2];
    const float* W1   = (const float*)d_in[3];
    const float* b1   = (const float*)d_in[4];
    const float* W2   = (const float*)d_in[5];
    const float* b2   = (const float*)d_in[6];
    const float* W3   = (const float*)d_in[7];
    const float* b3   = (const float*)d_in[8];
    const float* Wlin = (const float*)d_in[9];
    const float* blin = (const float*)d_in[10];
    float* out = (float*)d_out;

    const int EBLK = (N_EDGES + 255) / 256;
    const int NBLK = (N_NODES + 255) / 256;
    const int GEMM_BLK = (N_NODES + 127) / 128;
    const int AGG_BLK  = (N_NODES * 32 + 255) / 256;

    // dynamic smem: (2*128 + 2*64) rows * (K+8) bf16
    const int SMEM128 = 384 * (128 + 8) * 2;   // 104448
    const int SMEM64  = 384 * (64 + 8) * 2;    // 55296
    cudaFuncSetAttribute(gemm_mma_kernel<128>,
                         cudaFuncAttributeMaxDynamicSharedMemorySize, SMEM128);
    cudaFuncSetAttribute(gemm_mma_kernel<64>,
                         cudaFuncAttributeMaxDynamicSharedMemorySize, SMEM64);

    // launches 0..2: prep gemm1 doesn't depend on
    init_kernel<<<NBLK, 256>>>();                    // 0
    count_kernel<<<EBLK, 256>>>(ei);                 // 1
    scan1_kernel<<<N_SCAN_BLOCKS, SCAN_B>>>();       // 2

    // launch 3: big GEMM (x @ W1) — ncu capture slot
    gemm_mma_kernel<128><<<GEMM_BLK, 512, SMEM128>>>(x, W1, 0, N_NODES);  // 3

    // finish CSR build
    scan3_kernel<<<N_SCAN_BLOCKS, SCAN_B>>>();       // 4
    fill_kernel<<<EBLK, 256>>>(ei);                  // 5

    // layer 1 aggregation
    aggregate_kernel<<<AGG_BLK, 256>>>(b1, 1);
    // layer 2
    gemm_mma_kernel<64><<<GEMM_BLK, 512, SMEM64>>>(x, W2, 1, N_NODES);
    aggregate_kernel<<<AGG_BLK, 256>>>(b2, 1);
    // layer 3
    gemm_mma_kernel<64><<<GEMM_BLK, 512, SMEM64>>>(x, W3, 1, N_NODES);
    aggregate_kernel<<<AGG_BLK, 256>>>(b3, 0);

    // pool + head
    pool_kernel<<<(N_NODES + 511) / 512, 256>>>(batch);
    final_kernel<<<1, N_GRAPHS * N_OUT>>>(Wlin, blin, out);
}

// round 12
// speedup vs baseline: 1.1355x; 1.1355x over previous
#include <cuda_runtime.h>
#include <cuda_bf16.h>
#include <cuda_fp16.h>
#include <cstdint>

// Problem constants (fixed by the dataset)
#define N_NODES 100000
#define N_EDGES 1600000
#define N_FEAT  128
#define HIDDEN  64
#define N_OUT   10
#define N_GRAPHS 64

#define SCAN_B 1024
#define N_SCAN_BLOCKS ((N_NODES + SCAN_B - 1) / SCAN_B)   // 98

// ---------------- device scratch (static, no allocation) ----------------
__device__ int    g_deg[N_NODES];
__device__ float  g_dis[N_NODES];
__device__ int    g_rowptr[N_NODES + 1];
__device__ int    g_cursor[N_NODES];
__device__ int    g_scan_tmp[N_NODES];
__device__ int    g_bsum[N_SCAN_BLOCKS];
__device__ __align__(16) int2   g_csr_pack[N_EDGES];
__device__ __align__(16) __half g_tmpAh[(size_t)N_NODES * HIDDEN]; // h@W (fp16)
__device__ __align__(16) float  g_tmpB[(size_t)N_NODES * HIDDEN];  // aggregated h
__device__ float  g_pool_sums[N_GRAPHS * HIDDEN];
__device__ float  g_pool_cnt[N_GRAPHS];

// ---------------- init / CSR build (proven, round 8) --------------------
__global__ void init_kernel() {
    int i = blockIdx.x * blockDim.x + threadIdx.x;
    if (i < N_NODES) g_deg[i] = 1;
    if (i < N_GRAPHS * HIDDEN) g_pool_sums[i] = 0.f;
    if (i < N_GRAPHS) g_pool_cnt[i] = 0.f;
}

__global__ void count_kernel(const int* __restrict__ ei) {
    int e = blockIdx.x * blockDim.x + threadIdx.x;
    if (e < N_EDGES) atomicAdd(&g_deg[ei[e + N_EDGES]], 1);
}

__global__ void scan1_kernel() {
    __shared__ int s[SCAN_B];
    int tid = threadIdx.x;
    int i = blockIdx.x * SCAN_B + tid;
    int deg = (i < N_NODES) ? g_deg[i] : 1;
    if (i < N_NODES) g_dis[i] = rsqrtf((float)deg);
    int v = deg - 1;
    s[tid] = v;
    __syncthreads();
    #pragma unroll
    for (int off = 1; off < SCAN_B; off <<= 1) {
        int t = (tid >= off) ? s[tid - off] : 0;
        __syncthreads();
        s[tid] += t;
        __syncthreads();
    }
    if (i < N_NODES) g_scan_tmp[i] = s[tid] - v;
    if (tid == SCAN_B - 1) g_bsum[blockIdx.x] = s[tid];
}

__global__ void scan3_kernel() {
    __shared__ int base;
    if (threadIdx.x == 0) {
        int run = 0;
        for (int b = 0; b < blockIdx.x; b++) run += g_bsum[b];
        base = run;
        if (blockIdx.x == 0) g_rowptr[N_NODES] = N_EDGES;
    }
    __syncthreads();
    int i = blockIdx.x * SCAN_B + threadIdx.x;
    if (i < N_NODES) {
        int v = g_scan_tmp[i] + base;
        g_rowptr[i] = v;
        g_cursor[i] = v;
    }
}

__global__ void fill_kernel(const int* __restrict__ ei) {
    int e = blockIdx.x * blockDim.x + threadIdx.x;
    if (e < N_EDGES) {
        int r = ei[e];
        int c = ei[e + N_EDGES];
        int pos = atomicAdd(&g_cursor[c], 1);
        float nr = g_dis[r] * g_dis[c];
        g_csr_pack[pos] = make_int2(r, __float_as_int(nr));
    }
}

// ---------------- SGEMM (scalar FFMA, round-8 proven shape) --------------
// C[M,64] = A[M,K] @ W[K,64], fp32 compute, output stored as fp16.
// A = x (sel==0) or g_tmpB (sel==1).  128x64 block tile, 256 threads.
// Microtile 8 rows x 4 cols: ty=tid>>4 -> rows ty*8..+7; tx=tid&15 -> cols tx*4..+3.
template <int K>
__global__ __launch_bounds__(256)
void gemm_kernel(const float* __restrict__ x, const float* __restrict__ W,
                 int sel, int M) {
    constexpr int KC = 32;
    __shared__ __align__(16) float Ws[K * 64];      // <=32KB
    __shared__ __align__(16) float As[KC * 128];    // 16KB, As[kloc][row]

    const float* __restrict__ A = (sel == 0) ? x : (const float*)g_tmpB;
    __half* __restrict__ C = g_tmpAh;

    const int tid = threadIdx.x;
    const int tx = tid & 15;    // cols tx*4 .. tx*4+3
    const int ty = tid >> 4;    // rows ty*8 .. ty*8+7
    const int row0 = blockIdx.x * 128;

    for (int i = tid; i < K * 16; i += 256)
        *(float4*)(Ws + i * 4) = *(const float4*)(W + i * 4);

    float acc[8][4];
    #pragma unroll
    for (int r = 0; r < 8; r++)
        #pragma unroll
        for (int c = 0; c < 4; c++) acc[r][c] = 0.f;

    for (int kk = 0; kk < K; kk += KC) {
        __syncthreads();
        #pragma unroll
        for (int p = 0; p < 4; p++) {
            int slot = tid + p * 256;    // 0..1023
            int r = slot >> 3;           // 0..127
            int q = slot & 7;            // 0..7 (float4 along K)
            int grow = row0 + r;
            float4 v = make_float4(0.f, 0.f, 0.f, 0.f);
            if (grow < M)
                v = *(const float4*)(A + (size_t)grow * K + kk + q * 4);
            As[(q * 4 + 0) * 128 + r] = v.x;
            As[(q * 4 + 1) * 128 + r] = v.y;
            As[(q * 4 + 2) * 128 + r] = v.z;
            As[(q * 4 + 3) * 128 + r] = v.w;
        }
        __syncthreads();
        #pragma unroll
        for (int k = 0; k < KC; k++) {
            const float* ap = As + k * 128 + ty * 8;
            float4 alo = *(const float4*)(ap);
            float4 ahi = *(const float4*)(ap + 4);
            float4 b   = *(const float4*)(Ws + (size_t)(kk + k) * 64 + tx * 4);
            float a[8] = {alo.x, alo.y, alo.z, alo.w, ahi.x, ahi.y, ahi.z, ahi.w};
            #pragma unroll
            for (int r = 0; r < 8; r++) {
                acc[r][0] += a[r] * b.x;
                acc[r][1] += a[r] * b.y;
                acc[r][2] += a[r] * b.z;
                acc[r][3] += a[r] * b.w;
            }
        }
    }

    #pragma unroll
    for (int r = 0; r < 8; r++) {
        int grow = row0 + ty * 8 + r;
        if (grow < M) {
            __half2 h01 = __floats2half2_rn(acc[r][0], acc[r][1]);
            __half2 h23 = __floats2half2_rn(acc[r][2], acc[r][3]);
            uint2 pk;
            pk.x = *(uint32_t*)&h01;
            pk.y = *(uint32_t*)&h23;
            *(uint2*)(C + (size_t)grow * 64 + tx * 4) = pk;
        }
    }
}

// ---------------- aggregation: fp16 gather, fp32 accumulate --------------
// g_tmpB[i] = sum_in(tmpAh[src]*norm) + tmpAh[i]/deg + b, optional relu.
// one warp per node; lane owns 2 consecutive features (one half2)
__global__ void aggregate_kernel(const float* __restrict__ bias, int relu) {
    int warp = (blockIdx.x * blockDim.x + threadIdx.x) >> 5;
    if (warp >= N_NODES) return;
    int lane = threadIdx.x & 31;

    const __half* __restrict__ hW = g_tmpAh;
    float* __restrict__ out = g_tmpB;

    int start = g_rowptr[warp];
    int end   = g_rowptr[warp + 1];
    float d = g_dis[warp];
    float w = d * d;   // self loop weight = 1/deg

    float2 sf = __half22float2(*(const __half2*)(hW + (size_t)warp * 64 + lane * 2));
    float ax = sf.x * w, ay = sf.y * w;

    for (int k = start; k < end; k++) {
        int2 p = g_csr_pack[k];
        float nr = __int_as_float(p.y);
        float2 vf = __half22float2(*(const __half2*)(hW + (size_t)p.x * 64 + lane * 2));
        ax += vf.x * nr;
        ay += vf.y * nr;
    }

    ax += bias[lane * 2];
    ay += bias[lane * 2 + 1];
    if (relu) { ax = fmaxf(ax, 0.f); ay = fmaxf(ay, 0.f); }
    *(float2*)(out + (size_t)warp * 64 + lane * 2) = make_float2(ax, ay);
}

// ---------------- mean pool over sorted batch ----------------------------
__global__ void pool_kernel(const int* __restrict__ batch) {
    const float* __restrict__ h = g_tmpB;
    int col  = threadIdx.x & 63;
    int slot = threadIdx.x >> 6;
    int n0 = blockIdx.x * 512 + slot * 128;
    if (n0 >= N_NODES) return;
    int n1 = min(n0 + 128, N_NODES);

    float acc = 0.f, cnt = 0.f;
    int cur = batch[n0];
    for (int i = n0; i < n1; i++) {
        int g = batch[i];
        if (g != cur) {
            atomicAdd(&g_pool_sums[cur * 64 + col], acc);
            if (col == 0) atomicAdd(&g_pool_cnt[cur], cnt);
            cur = g; acc = 0.f; cnt = 0.f;
        }
        acc += h[(size_t)i * 64 + col];
        cnt += 1.f;
    }
    atomicAdd(&g_pool_sums[cur * 64 + col], acc);
    if (col == 0) atomicAdd(&g_pool_cnt[cur], cnt);
}

// ---------------- final linear -------------------------------------------
__global__ void final_kernel(const float* __restrict__ Wlin,
                             const float* __restrict__ blin,
                             float* __restrict__ out) {
    int tid = threadIdx.x;
    if (tid >= N_GRAPHS * N_OUT) return;
    int g = tid / N_OUT;
    int o = tid % N_OUT;
    float inv = 1.f / fmaxf(g_pool_cnt[g], 1.f);
    float acc = blin[o];
    #pragma unroll
    for (int c = 0; c < 64; c++)
        acc += g_pool_sums[g * 64 + c] * inv * Wlin[c * N_OUT + o];
    out[g * N_OUT + o] = acc;
}

// ---------------- launch --------------------------------------------------
extern "C" void kernel_launch(void* const* d_in, const int* in_sizes, int n_in,
                              void* d_out, int out_size) {
    const float* x    = (const float*)d_in[0];
    const int*   ei   = (const int*)d_in[1];
    const int*   batch= (const int*)d_in[2];
    const float* W1   = (const float*)d_in[3];
    const float* b1   = (const float*)d_in[4];
    const float* W2   = (const float*)d_in[5];
    const float* b2   = (const float*)d_in[6];
    const float* W3   = (const float*)d_in[7];
    const float* b3   = (const float*)d_in[8];
    const float* Wlin = (const float*)d_in[9];
    const float* blin = (const float*)d_in[10];
    float* out = (float*)d_out;

    const int EBLK = (N_EDGES + 255) / 256;
    const int NBLK = (N_NODES + 255) / 256;
    const int GEMM_BLK = (N_NODES + 127) / 128;
    const int AGG_BLK  = (N_NODES * 32 + 255) / 256;

    // launches 0..2: prep gemm1 doesn't depend on
    init_kernel<<<NBLK, 256>>>();                    // 0
    count_kernel<<<EBLK, 256>>>(ei);                 // 1
    scan1_kernel<<<N_SCAN_BLOCKS, SCAN_B>>>();       // 2

    // launch 3: big GEMM (x @ W1) — ncu capture slot
    gemm_kernel<128><<<GEMM_BLK, 256>>>(x, W1, 0, N_NODES);   // 3

    // finish CSR build
    scan3_kernel<<<N_SCAN_BLOCKS, SCAN_B>>>();       // 4
    fill_kernel<<<EBLK, 256>>>(ei);                  // 5

    // layer 1 aggregation
    aggregate_kernel<<<AGG_BLK, 256>>>(b1, 1);
    // layer 2
    gemm_kernel<64><<<GEMM_BLK, 256>>>(x, W2, 1, N_NODES);
    aggregate_kernel<<<AGG_BLK, 256>>>(b2, 1);
    // layer 3
    gemm_kernel<64><<<GEMM_BLK, 256>>>(x, W3, 1, N_NODES);
    aggregate_kernel<<<AGG_BLK, 256>>>(b3, 0);

    // pool + head
    pool_kernel<<<(N_NODES + 511) / 512, 256>>>(batch);
    final_kernel<<<1, N_GRAPHS * N_OUT>>>(Wlin, blin, out);
}